// round 1
// baseline (speedup 1.0000x reference)
#include <cuda_runtime.h>

// ---------------------------------------------------------------------------
// NALU: out = g*a + (1-g)*m
//   W = tanh(W_hat)*sigmoid(M_hat)
//   a = x @ W
//   m = exp(log(|x|+eps) @ W)
//   g = sigmoid(x @ gate)
// Shapes: x [8192,2048], W/M/gate [2048,2048], out [8192,2048], all fp32.
// ---------------------------------------------------------------------------

#define NALU_EPS 1e-7f

static const int BB  = 8192;
static const int DIN = 2048;
static const int DOUT= 2048;

// Scratch (allocation-free rule -> __device__ globals)
__device__ float g_W   [2048u * 2048u];   // fused weight
__device__ float g_L   [8192u * 2048u];   // log(|x|+eps)
__device__ float g_Abuf[8192u * 2048u];   // x @ W
__device__ float g_Mbuf[8192u * 2048u];   // L @ W   (pre-exp)
__device__ float g_Gbuf[8192u * 2048u];   // x @ gate (pre-sigmoid)

// ---------------------------------------------------------------------------
// Prep kernels
// ---------------------------------------------------------------------------
__global__ void prep_w_kernel(const float* __restrict__ Wh,
                              const float* __restrict__ Mh, int n4)
{
    int i = blockIdx.x * blockDim.x + threadIdx.x;
    if (i < n4) {
        float4 w = ((const float4*)Wh)[i];
        float4 m = ((const float4*)Mh)[i];
        float4 o;
        o.x = tanhf(w.x) * (1.f / (1.f + expf(-m.x)));
        o.y = tanhf(w.y) * (1.f / (1.f + expf(-m.y)));
        o.z = tanhf(w.z) * (1.f / (1.f + expf(-m.z)));
        o.w = tanhf(w.w) * (1.f / (1.f + expf(-m.w)));
        ((float4*)g_W)[i] = o;
    }
}

__global__ void prep_l_kernel(const float* __restrict__ x, int n4)
{
    int i = blockIdx.x * blockDim.x + threadIdx.x;
    if (i < n4) {
        float4 v = ((const float4*)x)[i];
        float4 o;
        o.x = logf(fabsf(v.x) + NALU_EPS);
        o.y = logf(fabsf(v.y) + NALU_EPS);
        o.z = logf(fabsf(v.z) + NALU_EPS);
        o.w = logf(fabsf(v.w) + NALU_EPS);
        ((float4*)g_L)[i] = o;
    }
}

__global__ void epilogue_kernel(float* __restrict__ out, int n4)
{
    int i = blockIdx.x * blockDim.x + threadIdx.x;
    if (i < n4) {
        float4 a  = ((const float4*)g_Abuf)[i];
        float4 ml = ((const float4*)g_Mbuf)[i];
        float4 gl = ((const float4*)g_Gbuf)[i];
        float4 o;
        {
            float g = 1.f / (1.f + expf(-gl.x));
            o.x = g * a.x + (1.f - g) * expf(ml.x);
        }
        {
            float g = 1.f / (1.f + expf(-gl.y));
            o.y = g * a.y + (1.f - g) * expf(ml.y);
        }
        {
            float g = 1.f / (1.f + expf(-gl.z));
            o.z = g * a.z + (1.f - g) * expf(ml.z);
        }
        {
            float g = 1.f / (1.f + expf(-gl.w));
            o.w = g * a.w + (1.f - g) * expf(ml.w);
        }
        ((float4*)out)[i] = o;
    }
}

// ---------------------------------------------------------------------------
// tf32 tensor-core GEMM: C[M,N] = A[M,K] @ B[K,N], row-major, fp32 in/out.
// Block tile 128x128, K-tile 32. 128 threads = 4 warps, each warp 64x64.
// mma.sync.aligned.m16n8k8.row.col.f32.tf32.tf32.f32
// ---------------------------------------------------------------------------
__device__ __forceinline__ unsigned f2tf32(float f)
{
    unsigned u;
    asm("cvt.rna.tf32.f32 %0, %1;" : "=r"(u) : "f"(f));
    return u;
}

#define AS_STRIDE 36   // 32 + 4 pad (keeps uint4 alignment, kills LDS conflicts)
#define BS_STRIDE 132  // 128 + 4 pad

__device__ __forceinline__ void gemm_tf32_core(
    const float* __restrict__ A, const float* __restrict__ B,
    float* __restrict__ C, int M, int N, int K)
{
    __shared__ unsigned As[128 * AS_STRIDE]; // [m][k]
    __shared__ unsigned Bs[32 * BS_STRIDE]; // [k][n]

    const int tid  = threadIdx.x;
    const int lane = tid & 31;
    const int warp = tid >> 5;
    const int wm   = (warp & 1) * 64;   // warp row offset in block tile
    const int wn   = (warp >> 1) * 64;  // warp col offset in block tile
    const int g    = lane >> 2;         // group id 0..7
    const int tg   = lane & 3;          // thread-in-group 0..3

    const int bm = blockIdx.y * 128;
    const int bn = blockIdx.x * 128;

    float acc[4][8][4];
#pragma unroll
    for (int mt = 0; mt < 4; mt++)
#pragma unroll
        for (int nt = 0; nt < 8; nt++)
#pragma unroll
            for (int r = 0; r < 4; r++) acc[mt][nt][r] = 0.f;

    // global->shared mapping
    const int a_c  = tid & 7;   // float4 column within 32-wide k (0..7)
    const int a_r0 = tid >> 3;  // 0..15, step 16
    const int b_c  = tid & 31;  // float4 column within 128-wide n (0..31)
    const int b_r0 = tid >> 5;  // 0..3,  step 4

    for (int k0 = 0; k0 < K; k0 += 32) {
        // ---- load A tile (128 x 32), convert to tf32 ----
#pragma unroll
        for (int rr = 0; rr < 128; rr += 16) {
            const int r = a_r0 + rr;
            float4 v = *(const float4*)&A[(size_t)(bm + r) * K + k0 + a_c * 4];
            uint4 u;
            u.x = f2tf32(v.x); u.y = f2tf32(v.y);
            u.z = f2tf32(v.z); u.w = f2tf32(v.w);
            *(uint4*)&As[r * AS_STRIDE + a_c * 4] = u;
        }
        // ---- load B tile (32 x 128), convert to tf32 ----
#pragma unroll
        for (int rr = 0; rr < 32; rr += 4) {
            const int r = b_r0 + rr;
            float4 v = *(const float4*)&B[(size_t)(k0 + r) * N + bn + b_c * 4];
            uint4 u;
            u.x = f2tf32(v.x); u.y = f2tf32(v.y);
            u.z = f2tf32(v.z); u.w = f2tf32(v.w);
            *(uint4*)&Bs[r * BS_STRIDE + b_c * 4] = u;
        }
        __syncthreads();

#pragma unroll
        for (int kk = 0; kk < 4; kk++) {
            const int kb = kk * 8;
            unsigned a[4][4], b[8][2];
#pragma unroll
            for (int mt = 0; mt < 4; mt++) {
                const int r = wm + mt * 16 + g;
                a[mt][0] = As[r * AS_STRIDE + kb + tg];
                a[mt][1] = As[(r + 8) * AS_STRIDE + kb + tg];
                a[mt][2] = As[r * AS_STRIDE + kb + tg + 4];
                a[mt][3] = As[(r + 8) * AS_STRIDE + kb + tg + 4];
            }
#pragma unroll
            for (int nt = 0; nt < 8; nt++) {
                const int c = wn + nt * 8 + g;
                b[nt][0] = Bs[(kb + tg) * BS_STRIDE + c];
                b[nt][1] = Bs[(kb + tg + 4) * BS_STRIDE + c];
            }
#pragma unroll
            for (int mt = 0; mt < 4; mt++)
#pragma unroll
                for (int nt = 0; nt < 8; nt++) {
                    asm volatile(
                        "mma.sync.aligned.m16n8k8.row.col.f32.tf32.tf32.f32 "
                        "{%0,%1,%2,%3}, {%4,%5,%6,%7}, {%8,%9}, {%0,%1,%2,%3};\n"
                        : "+f"(acc[mt][nt][0]), "+f"(acc[mt][nt][1]),
                          "+f"(acc[mt][nt][2]), "+f"(acc[mt][nt][3])
                        : "r"(a[mt][0]), "r"(a[mt][1]), "r"(a[mt][2]), "r"(a[mt][3]),
                          "r"(b[nt][0]), "r"(b[nt][1]));
                }
        }
        __syncthreads();
    }

    // ---- epilogue: write C ----
#pragma unroll
    for (int mt = 0; mt < 4; mt++) {
        const int r = bm + wm + mt * 16 + g;
#pragma unroll
        for (int nt = 0; nt < 8; nt++) {
            const int c = bn + wn + nt * 8 + 2 * tg;
            *(float2*)&C[(size_t)r * N + c] =
                make_float2(acc[mt][nt][0], acc[mt][nt][1]);
            *(float2*)&C[(size_t)(r + 8) * N + c] =
                make_float2(acc[mt][nt][2], acc[mt][nt][3]);
        }
    }
}

// Three instantiations binding the __device__ scratch buffers.
__global__ __launch_bounds__(128, 2)
void gemm_xw_kernel(const float* __restrict__ x, int M, int N, int K)
{
    gemm_tf32_core(x, g_W, g_Abuf, M, N, K);
}

__global__ __launch_bounds__(128, 2)
void gemm_lw_kernel(int M, int N, int K)
{
    gemm_tf32_core(g_L, g_W, g_Mbuf, M, N, K);
}

__global__ __launch_bounds__(128, 2)
void gemm_xg_kernel(const float* __restrict__ x,
                    const float* __restrict__ gate, int M, int N, int K)
{
    gemm_tf32_core(x, gate, g_Gbuf, M, N, K);
}

// ---------------------------------------------------------------------------
// Launch
// ---------------------------------------------------------------------------
extern "C" void kernel_launch(void* const* d_in, const int* in_sizes, int n_in,
                              void* d_out, int out_size)
{
    const float* x    = (const float*)d_in[0];
    const float* Wh   = (const float*)d_in[1];
    const float* Mh   = (const float*)d_in[2];
    const float* gate = (const float*)d_in[3];
    float* out = (float*)d_out;

    // prep: W = tanh(Wh)*sigmoid(Mh); L = log(|x|+eps)
    {
        int n4 = (DIN * DOUT) / 4;
        prep_w_kernel<<<(n4 + 255) / 256, 256>>>(Wh, Mh, n4);
    }
    {
        int n4 = (BB * DIN) / 4;
        prep_l_kernel<<<(n4 + 255) / 256, 256>>>(x, n4);
    }

    dim3 grid(DOUT / 128, BB / 128);
    gemm_xw_kernel<<<grid, 128>>>(x, BB, DOUT, DIN);
    gemm_lw_kernel<<<grid, 128>>>(BB, DOUT, DIN);
    gemm_xg_kernel<<<grid, 128>>>(x, gate, BB, DOUT, DIN);

    {
        int n4 = (BB * DOUT) / 4;
        epilogue_kernel<<<(n4 + 255) / 256, 256>>>(out, n4);
    }
}

// round 2
// speedup vs baseline: 1.1622x; 1.1622x over previous
#include <cuda_runtime.h>

// ---------------------------------------------------------------------------
// NALU: out = g*a + (1-g)*m
//   W = tanh(W_hat)*sigmoid(M_hat)
//   a = x @ W ; m = exp(log(|x|+eps) @ W) ; g = sigmoid(x @ gate)
// Shapes: x [8192,2048], W/M/gate [2048,2048], out [8192,2048], fp32.
// ---------------------------------------------------------------------------

#define NALU_EPS 1e-7f

static const int BB   = 8192;
static const int DIN  = 2048;
static const int DOUT = 2048;

// Scratch (allocation-free rule -> __device__ globals). tf32 bit patterns as u32.
__device__ unsigned g_Xt[8192u * 2048u];  // tf32(x)
__device__ unsigned g_L [8192u * 2048u];  // tf32(log(|x|+eps))
__device__ unsigned g_W [2048u * 2048u];  // tf32(tanh(Wh)*sig(Mh))
__device__ unsigned g_Gt[2048u * 2048u];  // tf32(gate)
__device__ float g_Abuf[8192u * 2048u];   // x @ W
__device__ float g_Mbuf[8192u * 2048u];   // L @ W (pre-exp)
__device__ float g_Gbuf[8192u * 2048u];   // x @ gate (pre-sigmoid)

__device__ __forceinline__ unsigned f2tf32(float f)
{
    unsigned u;
    asm("cvt.rna.tf32.f32 %0, %1;" : "=r"(u) : "f"(f));
    return u;
}

// ---------------------------------------------------------------------------
// Prep kernels
// ---------------------------------------------------------------------------
__global__ void prep_x_kernel(const float* __restrict__ x, int n4)
{
    int i = blockIdx.x * blockDim.x + threadIdx.x;
    if (i < n4) {
        float4 v = ((const float4*)x)[i];
        uint4 xt, lt;
        xt.x = f2tf32(v.x); xt.y = f2tf32(v.y); xt.z = f2tf32(v.z); xt.w = f2tf32(v.w);
        lt.x = f2tf32(logf(fabsf(v.x) + NALU_EPS));
        lt.y = f2tf32(logf(fabsf(v.y) + NALU_EPS));
        lt.z = f2tf32(logf(fabsf(v.z) + NALU_EPS));
        lt.w = f2tf32(logf(fabsf(v.w) + NALU_EPS));
        ((uint4*)g_Xt)[i] = xt;
        ((uint4*)g_L)[i]  = lt;
    }
}

__global__ void prep_w_kernel(const float* __restrict__ Wh,
                              const float* __restrict__ Mh,
                              const float* __restrict__ gate, int n4)
{
    int i = blockIdx.x * blockDim.x + threadIdx.x;
    if (i < n4) {
        float4 w = ((const float4*)Wh)[i];
        float4 m = ((const float4*)Mh)[i];
        float4 gt = ((const float4*)gate)[i];
        uint4 o, og;
        o.x = f2tf32(tanhf(w.x) * (1.f / (1.f + expf(-m.x))));
        o.y = f2tf32(tanhf(w.y) * (1.f / (1.f + expf(-m.y))));
        o.z = f2tf32(tanhf(w.z) * (1.f / (1.f + expf(-m.z))));
        o.w = f2tf32(tanhf(w.w) * (1.f / (1.f + expf(-m.w))));
        og.x = f2tf32(gt.x); og.y = f2tf32(gt.y);
        og.z = f2tf32(gt.z); og.w = f2tf32(gt.w);
        ((uint4*)g_W)[i]  = o;
        ((uint4*)g_Gt)[i] = og;
    }
}

__global__ void epilogue_kernel(float* __restrict__ out, int n4)
{
    int i = blockIdx.x * blockDim.x + threadIdx.x;
    if (i < n4) {
        float4 a  = ((const float4*)g_Abuf)[i];
        float4 ml = ((const float4*)g_Mbuf)[i];
        float4 gl = ((const float4*)g_Gbuf)[i];
        float4 o;
        { float g = 1.f / (1.f + expf(-gl.x)); o.x = g * a.x + (1.f - g) * expf(ml.x); }
        { float g = 1.f / (1.f + expf(-gl.y)); o.y = g * a.y + (1.f - g) * expf(ml.y); }
        { float g = 1.f / (1.f + expf(-gl.z)); o.z = g * a.z + (1.f - g) * expf(ml.z); }
        { float g = 1.f / (1.f + expf(-gl.w)); o.w = g * a.w + (1.f - g) * expf(ml.w); }
        ((float4*)out)[i] = o;
    }
}

// ---------------------------------------------------------------------------
// Pipelined tf32 tensor-core GEMM: C[M,N] = A[M,K] @ B[K,N], row-major.
// 256 threads = 8 warps. Block tile 128x128, K-tile 32, double-buffered cp.async.
// Warp tile 32x64 (warp grid 4x2). mma.sync.m16n8k8 tf32.
// ---------------------------------------------------------------------------
#define AS_STRIDE 36    // 32 + 4 pad  (A frag reads: 4r+tg -> 32 distinct banks)
#define BS_STRIDE 136   // 128 + 8 pad (B frag reads: 4tg+g+... stride%32==8 -> conflict-free)
#define ASZ (128 * AS_STRIDE)
#define BSZ (32 * BS_STRIDE)
#define GEMM_SMEM (2 * (ASZ + BSZ) * 4)
#define NKT 64          // K / 32

__device__ __forceinline__ void cp_async16(void* smem, const void* gmem)
{
    unsigned saddr = (unsigned)__cvta_generic_to_shared(smem);
    asm volatile("cp.async.cg.shared.global [%0], [%1], 16;\n"
                 :: "r"(saddr), "l"(gmem));
}
__device__ __forceinline__ void cp_commit()
{
    asm volatile("cp.async.commit_group;\n");
}
template <int N> __device__ __forceinline__ void cp_wait()
{
    asm volatile("cp.async.wait_group %0;\n" :: "n"(N));
}

__device__ __forceinline__ void gemm_tf32_pipe(
    const unsigned* __restrict__ A, const unsigned* __restrict__ B,
    float* __restrict__ C, int M, int N, int K)
{
    extern __shared__ unsigned smem[];
    unsigned* As = smem;              // [2][128][AS_STRIDE]
    unsigned* Bs = smem + 2 * ASZ;    // [2][32][BS_STRIDE]

    const int tid  = threadIdx.x;
    const int lane = tid & 31;
    const int warp = tid >> 5;
    const int wm   = (warp & 3) * 32;   // warp row offset
    const int wn   = (warp >> 2) * 64;  // warp col offset
    const int g    = lane >> 2;
    const int tg   = lane & 3;

    const int bm = blockIdx.y * 128;
    const int bn = blockIdx.x * 128;

    // cp.async mappings (16B per thread)
    const int a_r = tid >> 3;  // 0..31, step 32 (4 iters) -> 128 rows
    const int a_c = tid & 7;   // 16B chunk within 32-float row
    const int b_r = tid >> 5;  // 0..7, step 8 (4 iters) -> 32 rows
    const int b_c = tid & 31;  // 16B chunk within 128-float row

    float acc[2][8][4];
#pragma unroll
    for (int mt = 0; mt < 2; mt++)
#pragma unroll
        for (int nt = 0; nt < 8; nt++)
#pragma unroll
            for (int r = 0; r < 4; r++) acc[mt][nt][r] = 0.f;

    auto load_stage = [&](int kt, int s) {
        const int k0 = kt * 32;
        unsigned* as = As + s * ASZ;
        unsigned* bs = Bs + s * BSZ;
#pragma unroll
        for (int i = 0; i < 4; i++) {
            const int r = a_r + 32 * i;
            cp_async16(&as[r * AS_STRIDE + a_c * 4],
                       &A[(size_t)(bm + r) * K + k0 + a_c * 4]);
        }
#pragma unroll
        for (int i = 0; i < 4; i++) {
            const int r = b_r + 8 * i;
            cp_async16(&bs[r * BS_STRIDE + b_c * 4],
                       &B[(size_t)(k0 + r) * N + bn + b_c * 4]);
        }
    };

    load_stage(0, 0);
    cp_commit();

    for (int kt = 0; kt < NKT; kt++) {
        const int cur = kt & 1;
        if (kt + 1 < NKT) {
            load_stage(kt + 1, (kt + 1) & 1);
            cp_commit();
            cp_wait<1>();   // stage `cur` complete; newest may be in flight
        } else {
            cp_wait<0>();
        }
        __syncthreads();

        const unsigned* as = As + cur * ASZ;
        const unsigned* bs = Bs + cur * BSZ;
#pragma unroll
        for (int kk = 0; kk < 4; kk++) {
            const int kb = kk * 8;
            unsigned a[2][4], b[8][2];
#pragma unroll
            for (int mt = 0; mt < 2; mt++) {
                const int r = wm + mt * 16 + g;
                a[mt][0] = as[r * AS_STRIDE + kb + tg];
                a[mt][1] = as[(r + 8) * AS_STRIDE + kb + tg];
                a[mt][2] = as[r * AS_STRIDE + kb + tg + 4];
                a[mt][3] = as[(r + 8) * AS_STRIDE + kb + tg + 4];
            }
#pragma unroll
            for (int nt = 0; nt < 8; nt++) {
                const int c = wn + nt * 8 + g;
                b[nt][0] = bs[(kb + tg) * BS_STRIDE + c];
                b[nt][1] = bs[(kb + tg + 4) * BS_STRIDE + c];
            }
#pragma unroll
            for (int mt = 0; mt < 2; mt++)
#pragma unroll
                for (int nt = 0; nt < 8; nt++) {
                    asm volatile(
                        "mma.sync.aligned.m16n8k8.row.col.f32.tf32.tf32.f32 "
                        "{%0,%1,%2,%3}, {%4,%5,%6,%7}, {%8,%9}, {%0,%1,%2,%3};\n"
                        : "+f"(acc[mt][nt][0]), "+f"(acc[mt][nt][1]),
                          "+f"(acc[mt][nt][2]), "+f"(acc[mt][nt][3])
                        : "r"(a[mt][0]), "r"(a[mt][1]), "r"(a[mt][2]), "r"(a[mt][3]),
                          "r"(b[nt][0]), "r"(b[nt][1]));
                }
        }
        __syncthreads();
    }

    // epilogue
#pragma unroll
    for (int mt = 0; mt < 2; mt++) {
        const int r = bm + wm + mt * 16 + g;
#pragma unroll
        for (int nt = 0; nt < 8; nt++) {
            const int c = bn + wn + nt * 8 + 2 * tg;
            *(float2*)&C[(size_t)r * N + c] =
                make_float2(acc[mt][nt][0], acc[mt][nt][1]);
            *(float2*)&C[(size_t)(r + 8) * N + c] =
                make_float2(acc[mt][nt][2], acc[mt][nt][3]);
        }
    }
}

__global__ __launch_bounds__(256, 2)
void gemm_xw_kernel(int M, int N, int K)
{
    gemm_tf32_pipe(g_Xt, g_W, g_Abuf, M, N, K);
}
__global__ __launch_bounds__(256, 2)
void gemm_lw_kernel(int M, int N, int K)
{
    gemm_tf32_pipe(g_L, g_W, g_Mbuf, M, N, K);
}
__global__ __launch_bounds__(256, 2)
void gemm_xg_kernel(int M, int N, int K)
{
    gemm_tf32_pipe(g_Xt, g_Gt, g_Gbuf, M, N, K);
}

// ---------------------------------------------------------------------------
// Launch
// ---------------------------------------------------------------------------
extern "C" void kernel_launch(void* const* d_in, const int* in_sizes, int n_in,
                              void* d_out, int out_size)
{
    const float* x    = (const float*)d_in[0];
    const float* Wh   = (const float*)d_in[1];
    const float* Mh   = (const float*)d_in[2];
    const float* gate = (const float*)d_in[3];
    float* out = (float*)d_out;

    static bool attr_set = false;
    if (!attr_set) {
        cudaFuncSetAttribute(gemm_xw_kernel,
                             cudaFuncAttributeMaxDynamicSharedMemorySize, GEMM_SMEM);
        cudaFuncSetAttribute(gemm_lw_kernel,
                             cudaFuncAttributeMaxDynamicSharedMemorySize, GEMM_SMEM);
        cudaFuncSetAttribute(gemm_xg_kernel,
                             cudaFuncAttributeMaxDynamicSharedMemorySize, GEMM_SMEM);
        attr_set = true;
    }

    {
        int n4 = (BB * DIN) / 4;
        prep_x_kernel<<<(n4 + 255) / 256, 256>>>(x, n4);
    }
    {
        int n4 = (DIN * DOUT) / 4;
        prep_w_kernel<<<(n4 + 255) / 256, 256>>>(Wh, Mh, gate, n4);
    }

    dim3 grid(DOUT / 128, BB / 128);
    gemm_xw_kernel<<<grid, 256, GEMM_SMEM>>>(BB, DOUT, DIN);
    gemm_lw_kernel<<<grid, 256, GEMM_SMEM>>>(BB, DOUT, DIN);
    gemm_xg_kernel<<<grid, 256, GEMM_SMEM>>>(BB, DOUT, DIN);

    {
        int n4 = (BB * DOUT) / 4;
        epilogue_kernel<<<(n4 + 255) / 256, 256>>>(out, n4);
    }
}

// round 6
// speedup vs baseline: 1.1694x; 1.0062x over previous
#include <cuda_runtime.h>
#include <cstdint>

// ---------------------------------------------------------------------------
// NALU, tf32 mma.sync — R2-verified kernel + ONE change: fused NALU epilogue
// in the L@W GEMM (reads g_Abuf/g_Gbuf, writes out directly).
//   W = tanh(W_hat)*sigmoid(M_hat)
//   a = x @ W ; g_pre = x @ gate ; m_pre = L @ W
//   out = sig(g_pre)*a + (1-sig(g_pre))*exp(m_pre)
// ---------------------------------------------------------------------------

#define NALU_EPS 1e-7f
static const int BB = 8192, DIN = 2048, DOUT = 2048;

__device__ unsigned g_Xt[8192u * 2048u];  // tf32(x)             [M][K]
__device__ unsigned g_L [8192u * 2048u];  // tf32(log(|x|+eps))  [M][K]
__device__ unsigned g_W [2048u * 2048u];  // tf32(tanh*sig)      [K][N]
__device__ unsigned g_Gt[2048u * 2048u];  // tf32(gate)          [K][N]
__device__ float g_Abuf[8192u * 2048u];   // x @ W
__device__ float g_Gbuf[8192u * 2048u];   // x @ gate (pre-sigmoid)

__device__ __forceinline__ unsigned f2tf32(float f)
{
    unsigned u;
    asm("cvt.rna.tf32.f32 %0, %1;" : "=r"(u) : "f"(f));
    return u;
}

__device__ __forceinline__ void cp_async16(void* smem, const void* gmem)
{
    unsigned saddr = (unsigned)__cvta_generic_to_shared(smem);
    asm volatile("cp.async.cg.shared.global [%0], [%1], 16;\n"
                 :: "r"(saddr), "l"(gmem));
}
__device__ __forceinline__ void cp_commit()
{
    asm volatile("cp.async.commit_group;\n");
}
template <int N> __device__ __forceinline__ void cp_wait()
{
    asm volatile("cp.async.wait_group %0;\n" :: "n"(N));
}

// ---------------------------------------------------------------------------
// Prep kernels (verbatim R2)
// ---------------------------------------------------------------------------
__global__ void prep_x_kernel(const float* __restrict__ x, int n4)
{
    int i = blockIdx.x * blockDim.x + threadIdx.x;
    if (i < n4) {
        float4 v = ((const float4*)x)[i];
        uint4 xt, lt;
        xt.x = f2tf32(v.x); xt.y = f2tf32(v.y); xt.z = f2tf32(v.z); xt.w = f2tf32(v.w);
        lt.x = f2tf32(logf(fabsf(v.x) + NALU_EPS));
        lt.y = f2tf32(logf(fabsf(v.y) + NALU_EPS));
        lt.z = f2tf32(logf(fabsf(v.z) + NALU_EPS));
        lt.w = f2tf32(logf(fabsf(v.w) + NALU_EPS));
        ((uint4*)g_Xt)[i] = xt;
        ((uint4*)g_L)[i]  = lt;
    }
}

__global__ void prep_w_kernel(const float* __restrict__ Wh,
                              const float* __restrict__ Mh,
                              const float* __restrict__ gate, int n4)
{
    int i = blockIdx.x * blockDim.x + threadIdx.x;
    if (i < n4) {
        float4 w = ((const float4*)Wh)[i];
        float4 m = ((const float4*)Mh)[i];
        float4 gt = ((const float4*)gate)[i];
        uint4 o, og;
        o.x = f2tf32(tanhf(w.x) * (1.f / (1.f + expf(-m.x))));
        o.y = f2tf32(tanhf(w.y) * (1.f / (1.f + expf(-m.y))));
        o.z = f2tf32(tanhf(w.z) * (1.f / (1.f + expf(-m.z))));
        o.w = f2tf32(tanhf(w.w) * (1.f / (1.f + expf(-m.w))));
        og.x = f2tf32(gt.x); og.y = f2tf32(gt.y);
        og.z = f2tf32(gt.z); og.w = f2tf32(gt.w);
        ((uint4*)g_W)[i]  = o;
        ((uint4*)g_Gt)[i] = og;
    }
}

// ---------------------------------------------------------------------------
// tf32 GEMM — verbatim R2 core (2-stage cp.async, two barriers per k-tile).
// FUSE adds the NALU combine in the epilogue.
// ---------------------------------------------------------------------------
#define AS_STRIDE 36
#define BS_STRIDE 136
#define ASZ (128 * AS_STRIDE)
#define BSZ (32 * BS_STRIDE)
#define GEMM_SMEM (2 * (ASZ + BSZ) * 4)
#define NKT 64

template<bool FUSE>
__device__ __forceinline__ void gemm_tf32_pipe(
    const unsigned* __restrict__ A, const unsigned* __restrict__ B,
    float* __restrict__ C, int M, int N, int K)
{
    extern __shared__ unsigned smem[];
    unsigned* As = smem;
    unsigned* Bs = smem + 2 * ASZ;

    const int tid  = threadIdx.x;
    const int lane = tid & 31;
    const int warp = tid >> 5;
    const int wm   = (warp & 3) * 32;
    const int wn   = (warp >> 2) * 64;
    const int g    = lane >> 2;
    const int tg   = lane & 3;

    const int bm = blockIdx.y * 128;
    const int bn = blockIdx.x * 128;

    const int a_r = tid >> 3;
    const int a_c = tid & 7;
    const int b_r = tid >> 5;
    const int b_c = tid & 31;

    float acc[2][8][4];
#pragma unroll
    for (int mt = 0; mt < 2; mt++)
#pragma unroll
        for (int nt = 0; nt < 8; nt++)
#pragma unroll
            for (int r = 0; r < 4; r++) acc[mt][nt][r] = 0.f;

    auto load_stage = [&](int kt, int s) {
        const int k0 = kt * 32;
        unsigned* as = As + s * ASZ;
        unsigned* bs = Bs + s * BSZ;
#pragma unroll
        for (int i = 0; i < 4; i++) {
            const int r = a_r + 32 * i;
            cp_async16(&as[r * AS_STRIDE + a_c * 4],
                       &A[(size_t)(bm + r) * K + k0 + a_c * 4]);
        }
#pragma unroll
        for (int i = 0; i < 4; i++) {
            const int r = b_r + 8 * i;
            cp_async16(&bs[r * BS_STRIDE + b_c * 4],
                       &B[(size_t)(k0 + r) * N + bn + b_c * 4]);
        }
    };

    load_stage(0, 0);
    cp_commit();

    for (int kt = 0; kt < NKT; kt++) {
        const int cur = kt & 1;
        if (kt + 1 < NKT) {
            load_stage(kt + 1, (kt + 1) & 1);
            cp_commit();
            cp_wait<1>();
        } else {
            cp_wait<0>();
        }
        __syncthreads();

        const unsigned* as = As + cur * ASZ;
        const unsigned* bs = Bs + cur * BSZ;
#pragma unroll
        for (int kk = 0; kk < 4; kk++) {
            const int kb = kk * 8;
            unsigned a[2][4], b[8][2];
#pragma unroll
            for (int mt = 0; mt < 2; mt++) {
                const int r = wm + mt * 16 + g;
                a[mt][0] = as[r * AS_STRIDE + kb + tg];
                a[mt][1] = as[(r + 8) * AS_STRIDE + kb + tg];
                a[mt][2] = as[r * AS_STRIDE + kb + tg + 4];
                a[mt][3] = as[(r + 8) * AS_STRIDE + kb + tg + 4];
            }
#pragma unroll
            for (int nt = 0; nt < 8; nt++) {
                const int c = wn + nt * 8 + g;
                b[nt][0] = bs[(kb + tg) * BS_STRIDE + c];
                b[nt][1] = bs[(kb + tg + 4) * BS_STRIDE + c];
            }
#pragma unroll
            for (int mt = 0; mt < 2; mt++)
#pragma unroll
                for (int nt = 0; nt < 8; nt++) {
                    asm volatile(
                        "mma.sync.aligned.m16n8k8.row.col.f32.tf32.tf32.f32 "
                        "{%0,%1,%2,%3}, {%4,%5,%6,%7}, {%8,%9}, {%0,%1,%2,%3};\n"
                        : "+f"(acc[mt][nt][0]), "+f"(acc[mt][nt][1]),
                          "+f"(acc[mt][nt][2]), "+f"(acc[mt][nt][3])
                        : "r"(a[mt][0]), "r"(a[mt][1]), "r"(a[mt][2]), "r"(a[mt][3]),
                          "r"(b[nt][0]), "r"(b[nt][1]));
                }
        }
        __syncthreads();
    }

    // epilogue (store mapping verbatim R2; FUSE adds the NALU combine)
#pragma unroll
    for (int mt = 0; mt < 2; mt++) {
        const int r0 = bm + wm + mt * 16 + g;
#pragma unroll
        for (int nt = 0; nt < 8; nt++) {
            const int c = bn + wn + nt * 8 + 2 * tg;
            if (FUSE) {
#pragma unroll
                for (int h = 0; h < 2; h++) {
                    const int r = r0 + 8 * h;
                    float2 av = *(const float2*)&g_Abuf[(size_t)r * 2048 + c];
                    float2 gv = *(const float2*)&g_Gbuf[(size_t)r * 2048 + c];
                    float m0 = acc[mt][nt][2 * h];
                    float m1 = acc[mt][nt][2 * h + 1];
                    float2 o;
                    {
                        float sg = 1.f / (1.f + expf(-gv.x));
                        o.x = sg * av.x + (1.f - sg) * expf(m0);
                    }
                    {
                        float sg = 1.f / (1.f + expf(-gv.y));
                        o.y = sg * av.y + (1.f - sg) * expf(m1);
                    }
                    *(float2*)&C[(size_t)r * N + c] = o;
                }
            } else {
                *(float2*)&C[(size_t)r0 * N + c] =
                    make_float2(acc[mt][nt][0], acc[mt][nt][1]);
                *(float2*)&C[(size_t)(r0 + 8) * N + c] =
                    make_float2(acc[mt][nt][2], acc[mt][nt][3]);
            }
        }
    }
}

__global__ __launch_bounds__(256, 2)
void gemm_xw_kernel(int M, int N, int K)
{
    gemm_tf32_pipe<false>(g_Xt, g_W, g_Abuf, M, N, K);
}
__global__ __launch_bounds__(256, 2)
void gemm_xg_kernel(int M, int N, int K)
{
    gemm_tf32_pipe<false>(g_Xt, g_Gt, g_Gbuf, M, N, K);
}
__global__ __launch_bounds__(256, 2)
void gemm_lw_fused_kernel(float* __restrict__ out, int M, int N, int K)
{
    gemm_tf32_pipe<true>(g_L, g_W, out, M, N, K);
}

// ---------------------------------------------------------------------------
// Launch
// ---------------------------------------------------------------------------
extern "C" void kernel_launch(void* const* d_in, const int* in_sizes, int n_in,
                              void* d_out, int out_size)
{
    const float* x    = (const float*)d_in[0];
    const float* Wh   = (const float*)d_in[1];
    const float* Mh   = (const float*)d_in[2];
    const float* gate = (const float*)d_in[3];
    float* out = (float*)d_out;

    static bool attr_set = false;
    if (!attr_set) {
        cudaFuncSetAttribute(gemm_xw_kernel,
                             cudaFuncAttributeMaxDynamicSharedMemorySize, GEMM_SMEM);
        cudaFuncSetAttribute(gemm_xg_kernel,
                             cudaFuncAttributeMaxDynamicSharedMemorySize, GEMM_SMEM);
        cudaFuncSetAttribute(gemm_lw_fused_kernel,
                             cudaFuncAttributeMaxDynamicSharedMemorySize, GEMM_SMEM);
        attr_set = true;
    }

    {
        int n4 = (BB * DIN) / 4;
        prep_x_kernel<<<(n4 + 255) / 256, 256>>>(x, n4);
    }
    {
        int n4 = (DIN * DOUT) / 4;
        prep_w_kernel<<<(n4 + 255) / 256, 256>>>(Wh, Mh, gate, n4);
    }

    dim3 grid(DOUT / 128, BB / 128);
    gemm_xw_kernel<<<grid, 256, GEMM_SMEM>>>(BB, DOUT, DIN);
    gemm_xg_kernel<<<grid, 256, GEMM_SMEM>>>(BB, DOUT, DIN);
    gemm_lw_fused_kernel<<<grid, 256, GEMM_SMEM>>>(out, BB, DOUT, DIN);
}

// round 7
// speedup vs baseline: 2.1178x; 1.8111x over previous
#include <cuda_runtime.h>
#include <cuda_fp16.h>
#include <cstdint>

// ---------------------------------------------------------------------------
// NALU fused via fp16 mma.sync (m16n8k16):
//   W = tanh(W_hat)*sigmoid(M_hat)
//   GEMM1: AG = x @ [W | gate]   (N=4096)
//   GEMM2: m_pre = L @ W, fused epilogue:
//          out = sig(g)*a + (1-sig(g))*exp(m_pre)
// ALL __device__ scratch referenced ONLY in device code (never as launch args).
// ---------------------------------------------------------------------------

#define NALU_EPS 1e-7f
static const int BB = 8192, DIN = 2048, DOUT = 2048;

__device__ __half g_Xh[8192u * 2048u];   // fp16(x)            [M][K]
__device__ __half g_Lh[8192u * 2048u];   // fp16(log(|x|+eps)) [M][K]
__device__ __half g_WG[4096u * 2048u];   // [W^T ; gate^T]     [N2][K] k-contiguous
__device__ float  g_AG[8192u * 4096u];   // x @ [W|gate]       [M][4096]

// ---------------------------------------------------------------------------
// PTX helpers
// ---------------------------------------------------------------------------
__device__ __forceinline__ void cp_async16(void* smem, const void* gmem)
{
    unsigned saddr = (unsigned)__cvta_generic_to_shared(smem);
    asm volatile("cp.async.cg.shared.global [%0], [%1], 16;\n"
                 :: "r"(saddr), "l"(gmem));
}
__device__ __forceinline__ void cp_commit()
{
    asm volatile("cp.async.commit_group;\n");
}
template <int N> __device__ __forceinline__ void cp_wait()
{
    asm volatile("cp.async.wait_group %0;\n" :: "n"(N));
}

// ---------------------------------------------------------------------------
// Prep kernels
// ---------------------------------------------------------------------------
__global__ void prep_x_kernel(const float* __restrict__ x, int n4)
{
    int i = blockIdx.x * blockDim.x + threadIdx.x;
    if (i < n4) {
        float4 v = ((const float4*)x)[i];
        __half2 x0 = __floats2half2_rn(v.x, v.y);
        __half2 x1 = __floats2half2_rn(v.z, v.w);
        __half2 l0 = __floats2half2_rn(logf(fabsf(v.x) + NALU_EPS),
                                       logf(fabsf(v.y) + NALU_EPS));
        __half2 l1 = __floats2half2_rn(logf(fabsf(v.z) + NALU_EPS),
                                       logf(fabsf(v.w) + NALU_EPS));
        uint2 xo, lo;
        xo.x = *(unsigned*)&x0; xo.y = *(unsigned*)&x1;
        lo.x = *(unsigned*)&l0; lo.y = *(unsigned*)&l1;
        ((uint2*)g_Xh)[i] = xo;
        ((uint2*)g_Lh)[i] = lo;
    }
}

// Transpose+convert: g_WG[n][k] = fp16(tanh(Wh[k][n])*sig(Mh[k][n]));
//                    g_WG[2048+n][k] = fp16(gate[k][n])
__global__ void prep_wg_kernel(const float* __restrict__ Wh,
                               const float* __restrict__ Mh,
                               const float* __restrict__ gate)
{
    __shared__ __half tw[32][33];
    __shared__ __half tg_[32][33];
    const int kb = blockIdx.y * 32;
    const int nb = blockIdx.x * 32;
    const int tx = threadIdx.x, ty = threadIdx.y;

#pragma unroll
    for (int i = 0; i < 4; i++) {
        int k = kb + ty + i * 8;
        size_t idx = (size_t)k * 2048 + nb + tx;
        float w = Wh[idx], m = Mh[idx], gt = gate[idx];
        tw[ty + i * 8][tx]  = __float2half_rn(tanhf(w) * (1.f / (1.f + expf(-m))));
        tg_[ty + i * 8][tx] = __float2half_rn(gt);
    }
    __syncthreads();
#pragma unroll
    for (int i = 0; i < 4; i++) {
        int n = nb + ty + i * 8;
        g_WG[(size_t)n * 2048 + kb + tx]          = tw[tx][ty + i * 8];
        g_WG[(size_t)(2048 + n) * 2048 + kb + tx] = tg_[tx][ty + i * 8];
    }
}

// ---------------------------------------------------------------------------
// fp16 GEMM core: C[M,N] = A[M,K] @ B^T  (B stored [N][K], k-contiguous).
// Block 128x128, 8 warps (warp tile 32x64), K-tile 32, 4-stage cp.async.
// ---------------------------------------------------------------------------
#define KT 32
#define S_LD 40                          // smem row stride in halves
#define TILE_H (128 * S_LD)
#define STAGE_H (2 * TILE_H)
#define NSTAGE 4
#define GEMM_SMEM (NSTAGE * STAGE_H * 2) // 81920 B
#define NKT 64

template<bool FUSE>
__device__ __forceinline__ void gemm_f16_core(
    const __half* __restrict__ A, const __half* __restrict__ B,
    float* __restrict__ C, int ldc)
{
    extern __shared__ __half sm[];

    const int tid  = threadIdx.x;
    const int lane = tid & 31;
    const int warp = tid >> 5;
    const int wm   = (warp & 3) * 32;
    const int wn   = (warp >> 2) * 64;
    const int g    = lane >> 2;
    const int tg   = lane & 3;

    const int bm = blockIdx.y * 128;
    const int bn = blockIdx.x * 128;

    float acc[2][8][4];
#pragma unroll
    for (int mt = 0; mt < 2; mt++)
#pragma unroll
        for (int nt = 0; nt < 8; nt++)
#pragma unroll
            for (int r = 0; r < 4; r++) acc[mt][nt][r] = 0.f;

    const int l_r0 = tid >> 2;   // 0..63, two iters -> 128 rows
    const int l_c  = tid & 3;    // 16B chunk in 64B row

    auto load_stage = [&](int kt, int s) {
        const int k0 = kt * KT;
        __half* as = sm + s * STAGE_H;
        __half* bs = as + TILE_H;
#pragma unroll
        for (int i = 0; i < 2; i++) {
            const int r = l_r0 + 64 * i;
            cp_async16(&as[r * S_LD + l_c * 8],
                       &A[(size_t)(bm + r) * 2048 + k0 + l_c * 8]);
            cp_async16(&bs[r * S_LD + l_c * 8],
                       &B[(size_t)(bn + r) * 2048 + k0 + l_c * 8]);
        }
    };

    load_stage(0, 0); cp_commit();
    load_stage(1, 1); cp_commit();
    load_stage(2, 2); cp_commit();

    for (int kt = 0; kt < NKT; kt++) {
        cp_wait<2>();
        __syncthreads();

        const __half* as = sm + (kt & 3) * STAGE_H;
        const __half* bs = as + TILE_H;

#pragma unroll
        for (int kb = 0; kb < KT; kb += 16) {
            unsigned a[2][4], b[8][2];
#pragma unroll
            for (int mt = 0; mt < 2; mt++) {
                const int r = (wm + mt * 16 + g) * S_LD + kb + 2 * tg;
                a[mt][0] = *(const unsigned*)&as[r];
                a[mt][1] = *(const unsigned*)&as[r + 8 * S_LD];
                a[mt][2] = *(const unsigned*)&as[r + 8];
                a[mt][3] = *(const unsigned*)&as[r + 8 * S_LD + 8];
            }
#pragma unroll
            for (int nt = 0; nt < 8; nt++) {
                const int rb = (wn + nt * 8 + g) * S_LD + kb + 2 * tg;
                b[nt][0] = *(const unsigned*)&bs[rb];
                b[nt][1] = *(const unsigned*)&bs[rb + 8];
            }
#pragma unroll
            for (int mt = 0; mt < 2; mt++)
#pragma unroll
                for (int nt = 0; nt < 8; nt++) {
                    asm volatile(
                        "mma.sync.aligned.m16n8k16.row.col.f32.f16.f16.f32 "
                        "{%0,%1,%2,%3}, {%4,%5,%6,%7}, {%8,%9}, {%0,%1,%2,%3};\n"
                        : "+f"(acc[mt][nt][0]), "+f"(acc[mt][nt][1]),
                          "+f"(acc[mt][nt][2]), "+f"(acc[mt][nt][3])
                        : "r"(a[mt][0]), "r"(a[mt][1]), "r"(a[mt][2]), "r"(a[mt][3]),
                          "r"(b[nt][0]), "r"(b[nt][1]));
                }
        }

        if (kt + 3 < NKT) load_stage(kt + 3, (kt + 3) & 3);
        cp_commit();
    }

    // ---- epilogue ----
#pragma unroll
    for (int mt = 0; mt < 2; mt++) {
        const int r0 = bm + wm + mt * 16 + g;
#pragma unroll
        for (int nt = 0; nt < 8; nt++) {
            const int c = bn + wn + nt * 8 + 2 * tg;
            if (FUSE) {
#pragma unroll
                for (int h = 0; h < 2; h++) {
                    const int r = r0 + 8 * h;
                    float2 av = *(const float2*)&g_AG[(size_t)r * 4096 + c];
                    float2 gv = *(const float2*)&g_AG[(size_t)r * 4096 + c + 2048];
                    float2 o;
                    {
                        float sg = 1.f / (1.f + expf(-gv.x));
                        o.x = sg * av.x + (1.f - sg) * expf(acc[mt][nt][2 * h]);
                    }
                    {
                        float sg = 1.f / (1.f + expf(-gv.y));
                        o.y = sg * av.y + (1.f - sg) * expf(acc[mt][nt][2 * h + 1]);
                    }
                    *(float2*)&C[(size_t)r * ldc + c] = o;
                }
            } else {
                *(float2*)&C[(size_t)r0 * ldc + c] =
                    make_float2(acc[mt][nt][0], acc[mt][nt][1]);
                *(float2*)&C[(size_t)(r0 + 8) * ldc + c] =
                    make_float2(acc[mt][nt][2], acc[mt][nt][3]);
            }
        }
    }
}

// Wrappers: scratch pointers formed IN DEVICE CODE (never passed from host).
__global__ __launch_bounds__(256, 2)
void gemm1_kernel()
{
    gemm_f16_core<false>(g_Xh, g_WG, g_AG, 4096);
}
__global__ __launch_bounds__(256, 2)
void gemm2_kernel(float* __restrict__ out)
{
    gemm_f16_core<true>(g_Lh, g_WG, out, 2048);
}

// ---------------------------------------------------------------------------
// Launch
// ---------------------------------------------------------------------------
extern "C" void kernel_launch(void* const* d_in, const int* in_sizes, int n_in,
                              void* d_out, int out_size)
{
    const float* x    = (const float*)d_in[0];
    const float* Wh   = (const float*)d_in[1];
    const float* Mh   = (const float*)d_in[2];
    const float* gate = (const float*)d_in[3];
    float* out = (float*)d_out;

    static bool attr_set = false;
    if (!attr_set) {
        cudaFuncSetAttribute(gemm1_kernel,
                             cudaFuncAttributeMaxDynamicSharedMemorySize, GEMM_SMEM);
        cudaFuncSetAttribute(gemm2_kernel,
                             cudaFuncAttributeMaxDynamicSharedMemorySize, GEMM_SMEM);
        attr_set = true;
    }

    {
        int n4 = (BB * DIN) / 4;
        prep_x_kernel<<<(n4 + 255) / 256, 256>>>(x, n4);
    }
    {
        dim3 blk(32, 8), grd(DOUT / 32, DIN / 32);
        prep_wg_kernel<<<grd, blk>>>(Wh, Mh, gate);
    }

    {
        dim3 grid(4096 / 128, BB / 128);   // (32, 64)
        gemm1_kernel<<<grid, 256, GEMM_SMEM>>>();
    }
    {
        dim3 grid(2048 / 128, BB / 128);   // (16, 64)
        gemm2_kernel<<<grid, 256, GEMM_SMEM>>>(out);
    }
}